// round 12
// baseline (speedup 1.0000x reference)
#include <cuda_runtime.h>
#include <math.h>

#define SR_F        48000.0f
#define SOUND_SPEED 343.0f
#define MAX_ORDER   10
#define RIR_LEN     24000
#define TAPS        81
#define HALF        40
#define AXN         42            // axis-image table size (2*(2*10+1))
#define NVALID      1561          // #(ax,ay,az) triples with tot_order <= 10 (exact)
#define MAXB        8
#define RPW         2             // records per warp (R11: 4 -> 2 for occupancy)
#define WPB         8             // warps per block (256 threads)

// ---------------------------------------------------------------------------
// Compile-time table of valid axis-index triples (tot_order <= MAX_ORDER),
// packed as ax + 42*ay + 42*42*az. Batch-independent.
// ---------------------------------------------------------------------------
constexpr int axis_order_ct(int a) {
    int p = (a >= 21) ? 1 : 0;
    int n = a - 21 * p - 10;
    int o1 = n - p; if (o1 < 0) o1 = -o1;
    int o2 = n;     if (o2 < 0) o2 = -o2;
    return o1 + o2;
}

struct ValidTable {
    int v[NVALID];
    constexpr ValidTable() : v() {
        int ord[AXN] = {};
        for (int a = 0; a < AXN; ++a) ord[a] = axis_order_ct(a);
        int s = 0;
        for (int az = 0; az < AXN; ++az)
            for (int ay = 0; ay < AXN; ++ay)
                for (int ax = 0; ax < AXN; ++ax)
                    if (ord[ax] + ord[ay] + ord[az] <= MAX_ORDER)
                        v[s++] = ax + AXN * ay + AXN * AXN * az;
    }
};

__device__ const ValidTable VT = ValidTable();

__constant__ float BETA_POW[11] = {
    1.0f, 0.9f, 0.81f, 0.729f, 0.6561f, 0.59049f,
    0.531441f, 0.4782969f, 0.43046721f, 0.387420489f, 0.3486784401f
};

__device__ __forceinline__ void decode_axis(int a, float& sign, float& off, int& order)
{
    int p = (a >= 21) ? 1 : 0;
    int n = a - 21 * p - 10;
    sign  = (float)(1 - 2 * p);
    off   = (float)(2 * n);
    order = abs(n - p) + abs(n);
}

// ---------------------------------------------------------------------------
// Kernel 1: zero the RIR region of d_out (pure float4 stores, no loads on the
// hot path) and write origin.
// d_out layout: [B*RIR_LEN floats rir][B floats origin]
// ---------------------------------------------------------------------------
__global__ void __launch_bounds__(256)
zero_kernel(const float* __restrict__ in, float* __restrict__ out, int B, int n4)
{
    int i = blockIdx.x * blockDim.x + threadIdx.x;
    if (i < n4)
        ((float4*)out)[i] = make_float4(0.f, 0.f, 0.f, 0.f);
    if (i < B) {
        const float* row = in + i * 9;
        float rx = row[0] * 10.0f, ry = row[1] * 10.0f, rz = row[2] * 10.0f;
        float dx = (row[3] - row[6]) * rx;
        float dy = (row[4] - row[7]) * ry;
        float dz = (row[5] - row[8]) * rz;
        out[B * RIR_LEN + i] =
            40.0f + SR_F * sqrtf(dx * dx + dy * dy + dz * dz) / SOUND_SPEED;
    }
}

// ---------------------------------------------------------------------------
// Kernel 2: scatter (R8/R10 configuration, RPW=2 for occupancy).
// Each warp owns RPW consecutive records. Lanes 0..RPW-1 build the records
// (geometry -> 8 floats) into smem; then all 32 lanes scatter taps
// {lane, lane+32, lane+64} per record with per-thread window constants
// (3 sincospif per thread). Scalar atomicAdd into d_out.
// ---------------------------------------------------------------------------
__global__ void __launch_bounds__(256)
scatter_kernel(const float* __restrict__ in, float* __restrict__ out, int nrec)
{
    const int gtid = blockIdx.x * blockDim.x + threadIdx.x;
    const int w    = gtid >> 5;          // global warp id
    const int wloc = threadIdx.x >> 5;   // warp within block
    const int lane = threadIdx.x & 31;
    const int rec0 = w * RPW;

    __shared__ float4 s_rec[WPB][RPW][2];

    if (rec0 >= nrec) return;

    // ---- Build phase: lanes 0..RPW-1 each build one record ----
    if (lane < RPW && rec0 + lane < nrec) {
        int i = rec0 + lane;
        int b = i / NVALID;
        int s = i - b * NVALID;
        int img = VT.v[s];
        int ax = img % AXN;
        int ay = (img / AXN) % AXN;
        int az = img / (AXN * AXN);

        float sgx, ofx; int ox; decode_axis(ax, sgx, ofx, ox);
        float sgy, ofy; int oy; decode_axis(ay, sgy, ofy, oy);
        float sgz, ofz; int oz; decode_axis(az, sgz, ofz, oz);

        const float* row = in + b * 9;
        float rx = row[0] * 10.0f, ry = row[1] * 10.0f, rz = row[2] * 10.0f;
        float mx = row[3] * rx,    my = row[4] * ry,    mz = row[5] * rz;
        float sx = row[6] * rx,    sy = row[7] * ry,    sz = row[8] * rz;

        float dx = sgx * sx + ofx * rx - mx;
        float dy = sgy * sy + ofy * ry - my;
        float dz = sgz * sz + ofz * rz - mz;

        float dist = sqrtf(dx * dx + dy * dy + dz * dz);
        float tau  = SR_F * dist / SOUND_SPEED;
        float i0   = floorf(tau);
        float frac = tau - i0;

        const float INV_PI = 0.318309886183790672f;
        int  bofs   = b * RIR_LEN;
        int  end_g  = bofs + RIR_LEN;
        int  base   = (int)i0 + HALF;
        int  base_g = (base >= RIR_LEN) ? end_g : bofs + base;
        float amp = BETA_POW[ox + oy + oz] / (4.0f * 3.14159265358979323846f * dist);
        float c   = amp * sinpif(frac) * INV_PI;
        float bb  = (40.0f + frac) * (1.0f / 41.0f);
        float cw, sw;
        sincospif(bb, &sw, &cw);

        s_rec[wloc][lane][0] = make_float4(__int_as_float(base_g), frac, amp, c);
        s_rec[wloc][lane][1] = make_float4(cw, sw, __int_as_float(end_g), 0.0f);
    }
    __syncwarp();

    // ---- Per-thread constants (amortized over RPW records) ----
    // taps handled by this thread: lane, lane+32, lane+64 (if < 81)
    float ct[3], st[3];
    #pragma unroll
    for (int k = 0; k < 3; ++k) {
        float a = (float)(lane + 32 * k) * (1.0f / 41.0f);
        sincospif(a, &st[k], &ct[k]);
    }
    const float A0 = (float)(lane - HALF);           // tap - 40 for k=0
    const float sgn = (lane & 1) ? 1.0f : -1.0f;     // sinc sign, parity of tap

    int nr = nrec - rec0; if (nr > RPW) nr = RPW;

    #pragma unroll
    for (int j = 0; j < RPW; ++j) {
        if (j >= nr) break;
        float4 r0 = s_rec[wloc][j][0];
        float4 r1 = s_rec[wloc][j][1];
        int   base_g = __float_as_int(r0.x);
        float frac   = r0.y;
        float amp    = r0.z;
        float cc     = r0.w * sgn;       // signed numerator
        float cw     = r1.x;
        float sw     = r1.y;
        int   end_g  = __float_as_int(r1.z);

        #pragma unroll
        for (int k = 0; k < 3; ++k) {
            int tap = lane + 32 * k;
            if (k == 2 && lane > 16) break;          // tap >= 81
            int idx = base_g + tap;
            if (idx >= end_g) continue;

            float t = (A0 + (float)(32 * k)) - frac;
            float v;
            if (t == 0.0f) v = amp;                  // tap==40 && frac==0
            else           v = __fdividef(cc, t);
            if (tap == 0 && frac > 0.0f) v = 0.0f;   // |t| > HALF support edge

            float win = 0.5f + 0.5f * fmaf(ct[k], cw, st[k] * sw);
            atomicAdd(out + idx, v * win);
        }
    }
}

extern "C" void kernel_launch(void* const* d_in, const int* in_sizes, int n_in,
                              void* d_out, int out_size)
{
    const float* in = (const float*)d_in[0];
    float* out = (float*)d_out;
    int B = in_sizes[0] / 9;
    if (B > MAXB) B = MAXB;

    int n4 = B * (RIR_LEN / 4);                    // 48000 float4s
    zero_kernel<<<(n4 + 255) / 256, 256>>>(in, out, B, n4);

    int nrec   = B * NVALID;                       // 12488
    int nwarps = (nrec + RPW - 1) / RPW;           // 6244
    int blocks = (nwarps * 32 + 255) / 256;        // 781
    scatter_kernel<<<blocks, 256>>>(in, out, nrec);
}

// round 13
// speedup vs baseline: 1.1547x; 1.1547x over previous
#include <cuda_runtime.h>
#include <math.h>

#define SR_F        48000.0f
#define SOUND_SPEED 343.0f
#define MAX_ORDER   10
#define RIR_LEN     24000
#define TAPS        81
#define HALF        40
#define AXN         42            // axis-image table size (2*(2*10+1))
#define NVALID      1561          // #(ax,ay,az) triples with tot_order <= 10 (exact)
#define MAXB        8
#define RPW         4             // records per warp (best measured config)
#define WPB         8             // warps per block (256 threads)

// ---------------------------------------------------------------------------
// Compile-time table of valid axis-index triples (tot_order <= MAX_ORDER),
// packed as ax + 42*ay + 42*42*az. Batch-independent.
// ---------------------------------------------------------------------------
constexpr int axis_order_ct(int a) {
    int p = (a >= 21) ? 1 : 0;
    int n = a - 21 * p - 10;
    int o1 = n - p; if (o1 < 0) o1 = -o1;
    int o2 = n;     if (o2 < 0) o2 = -o2;
    return o1 + o2;
}

struct ValidTable {
    int v[NVALID];
    constexpr ValidTable() : v() {
        int ord[AXN] = {};
        for (int a = 0; a < AXN; ++a) ord[a] = axis_order_ct(a);
        int s = 0;
        for (int az = 0; az < AXN; ++az)
            for (int ay = 0; ay < AXN; ++ay)
                for (int ax = 0; ax < AXN; ++ax)
                    if (ord[ax] + ord[ay] + ord[az] <= MAX_ORDER)
                        v[s++] = ax + AXN * ay + AXN * AXN * az;
    }
};

__device__ const ValidTable VT = ValidTable();

// ---------------------------------------------------------------------------
// Compile-time window table: {0.5*cos, 0.5*sin}(pi*k/41), k = 0..80.
// Taylor series in double after range reduction to (-pi, pi]; error << 1 ulp f32.
// ---------------------------------------------------------------------------
constexpr double ct_sin(double x) {   // |x| <= pi
    double term = x, sum = x;
    for (int n = 1; n < 20; ++n) {
        term *= -x * x / (double)((2 * n) * (2 * n + 1));
        sum += term;
    }
    return sum;
}
constexpr double ct_cos(double x) {   // |x| <= pi
    double term = 1.0, sum = 1.0;
    for (int n = 1; n < 20; ++n) {
        term *= -x * x / (double)((2 * n - 1) * (2 * n));
        sum += term;
    }
    return sum;
}

struct WinTable {
    float c[TAPS];   // 0.5*cos(pi*k/41)
    float s[TAPS];   // 0.5*sin(pi*k/41)
    constexpr WinTable() : c(), s() {
        const double PI = 3.14159265358979323846;
        for (int k = 0; k < TAPS; ++k) {
            double x = PI * (double)k / 41.0;
            if (x > PI) x -= 2.0 * PI;        // reduce to (-pi, pi]
            c[k] = (float)(0.5 * ct_cos(x));
            s[k] = (float)(0.5 * ct_sin(x));
        }
    }
};

__device__ const WinTable WT = WinTable();

__constant__ float BETA_POW[11] = {
    1.0f, 0.9f, 0.81f, 0.729f, 0.6561f, 0.59049f,
    0.531441f, 0.4782969f, 0.43046721f, 0.387420489f, 0.3486784401f
};

__device__ __forceinline__ void decode_axis(int a, float& sign, float& off, int& order)
{
    int p = (a >= 21) ? 1 : 0;
    int n = a - 21 * p - 10;
    sign  = (float)(1 - 2 * p);
    off   = (float)(2 * n);
    order = abs(n - p) + abs(n);
}

// ---------------------------------------------------------------------------
// Kernel 1: zero the RIR region of d_out (pure float4 stores) and write origin.
// d_out layout: [B*RIR_LEN floats rir][B floats origin]
// ---------------------------------------------------------------------------
__global__ void __launch_bounds__(256)
zero_kernel(const float* __restrict__ in, float* __restrict__ out, int B, int n4)
{
    int i = blockIdx.x * blockDim.x + threadIdx.x;
    if (i < n4)
        ((float4*)out)[i] = make_float4(0.f, 0.f, 0.f, 0.f);
    if (i < B) {
        const float* row = in + i * 9;
        float rx = row[0] * 10.0f, ry = row[1] * 10.0f, rz = row[2] * 10.0f;
        float dx = (row[3] - row[6]) * rx;
        float dy = (row[4] - row[7]) * ry;
        float dz = (row[5] - row[8]) * rz;
        out[B * RIR_LEN + i] =
            40.0f + SR_F * sqrtf(dx * dx + dy * dy + dz * dz) / SOUND_SPEED;
    }
}

// ---------------------------------------------------------------------------
// Kernel 2: scatter (R10 structure, RPW=4). Per-thread window constants now
// come from the compile-time table (6 L1-cached loads) instead of sincospif.
// ---------------------------------------------------------------------------
__global__ void __launch_bounds__(256)
scatter_kernel(const float* __restrict__ in, float* __restrict__ out, int nrec)
{
    const int gtid = blockIdx.x * blockDim.x + threadIdx.x;
    const int w    = gtid >> 5;          // global warp id
    const int wloc = threadIdx.x >> 5;   // warp within block
    const int lane = threadIdx.x & 31;
    const int rec0 = w * RPW;

    __shared__ float4 s_rec[WPB][RPW][2];

    if (rec0 >= nrec) return;

    // ---- Build phase: lanes 0..RPW-1 each build one record ----
    if (lane < RPW && rec0 + lane < nrec) {
        int i = rec0 + lane;
        int b = i / NVALID;
        int s = i - b * NVALID;
        int img = VT.v[s];
        int ax = img % AXN;
        int ay = (img / AXN) % AXN;
        int az = img / (AXN * AXN);

        float sgx, ofx; int ox; decode_axis(ax, sgx, ofx, ox);
        float sgy, ofy; int oy; decode_axis(ay, sgy, ofy, oy);
        float sgz, ofz; int oz; decode_axis(az, sgz, ofz, oz);

        const float* row = in + b * 9;
        float rx = row[0] * 10.0f, ry = row[1] * 10.0f, rz = row[2] * 10.0f;
        float mx = row[3] * rx,    my = row[4] * ry,    mz = row[5] * rz;
        float sx = row[6] * rx,    sy = row[7] * ry,    sz = row[8] * rz;

        float dx = sgx * sx + ofx * rx - mx;
        float dy = sgy * sy + ofy * ry - my;
        float dz = sgz * sz + ofz * rz - mz;

        float dist = sqrtf(dx * dx + dy * dy + dz * dz);
        float tau  = SR_F * dist / SOUND_SPEED;
        float i0   = floorf(tau);
        float frac = tau - i0;

        const float INV_PI = 0.318309886183790672f;
        int  bofs   = b * RIR_LEN;
        int  end_g  = bofs + RIR_LEN;
        int  base   = (int)i0 + HALF;
        int  base_g = (base >= RIR_LEN) ? end_g : bofs + base;
        float amp = BETA_POW[ox + oy + oz] / (4.0f * 3.14159265358979323846f * dist);
        float c   = amp * sinpif(frac) * INV_PI;
        float bb  = (40.0f + frac) * (1.0f / 41.0f);
        float cw, sw;
        sincospif(bb, &sw, &cw);

        s_rec[wloc][lane][0] = make_float4(__int_as_float(base_g), frac, amp, c);
        s_rec[wloc][lane][1] = make_float4(cw, sw, __int_as_float(end_g), 0.0f);
    }
    __syncwarp();

    // ---- Per-thread window constants from the compile-time table ----
    // taps handled by this thread: lane, lane+32, lane+64 (clamped; k=2
    // inactive for lane > 16, so the clamp only avoids an OOB load)
    float ct[3], st[3];
    #pragma unroll
    for (int k = 0; k < 3; ++k) {
        int tap = lane + 32 * k; if (tap > 80) tap = 80;
        ct[k] = __ldg(&WT.c[tap]);
        st[k] = __ldg(&WT.s[tap]);
    }
    const float A0 = (float)(lane - HALF);           // tap - 40 for k=0
    const float sgn = (lane & 1) ? 1.0f : -1.0f;     // sinc sign, parity of tap

    int nr = nrec - rec0; if (nr > RPW) nr = RPW;

    for (int j = 0; j < nr; ++j) {
        float4 r0 = s_rec[wloc][j][0];
        float4 r1 = s_rec[wloc][j][1];
        int   base_g = __float_as_int(r0.x);
        float frac   = r0.y;
        float amp    = r0.z;
        float cc     = r0.w * sgn;       // signed numerator
        float cw     = r1.x;
        float sw     = r1.y;
        int   end_g  = __float_as_int(r1.z);

        #pragma unroll
        for (int k = 0; k < 3; ++k) {
            int tap = lane + 32 * k;
            if (k == 2 && lane > 16) break;          // tap >= 81
            int idx = base_g + tap;
            if (idx >= end_g) continue;

            float t = (A0 + (float)(32 * k)) - frac;
            float v;
            if (t == 0.0f) v = amp;                  // tap==40 && frac==0
            else           v = __fdividef(cc, t);
            if (tap == 0 && frac > 0.0f) v = 0.0f;   // |t| > HALF support edge

            float win = fmaf(ct[k], cw, fmaf(st[k], sw, 0.5f));
            atomicAdd(out + idx, v * win);
        }
    }
}

extern "C" void kernel_launch(void* const* d_in, const int* in_sizes, int n_in,
                              void* d_out, int out_size)
{
    const float* in = (const float*)d_in[0];
    float* out = (float*)d_out;
    int B = in_sizes[0] / 9;
    if (B > MAXB) B = MAXB;

    int n4 = B * (RIR_LEN / 4);                    // 48000 float4s
    zero_kernel<<<(n4 + 255) / 256, 256>>>(in, out, B, n4);

    int nrec   = B * NVALID;                       // 12488
    int nwarps = (nrec + RPW - 1) / RPW;           // 3122
    int blocks = (nwarps * 32 + 255) / 256;        // 391
    scatter_kernel<<<blocks, 256>>>(in, out, nrec);
}